// round 7
// baseline (speedup 1.0000x reference)
#include <cuda_runtime.h>
#include <cuda_fp16.h>
#include <cstdint>

#define N_NODES 100000
#define N_EDGES 1600000
#define D_FEAT  128
#define N_POOL  25000
#define D4      (D_FEAT / 4)          // 32 float4 per row -> one warp per row
#define SCAN_B  1024
#define NBLK    ((N_NODES + SCAN_B - 1) / SCAN_B)   // 98

// ---- scratch (__device__ globals; allocation is forbidden) ----------------
__device__ float  g_Y[(size_t)N_NODES * D_FEAT];  // hop-1 result: x + agg1
__device__ float  g_Z[(size_t)N_NODES * D_FEAT];  // hop-2 result at flagged nodes
__device__ __half g_xh[(size_t)N_NODES * D_FEAT]; // fp16 copy of x (hop-1 gather)
__device__ int    g_cnt[N_NODES];                 // in-degree histogram
__device__ int    g_off[N_NODES];                 // CSR row offsets (exclusive)
__device__ int    g_cur[N_NODES];                 // write cursors for reorder
__device__ int    g_bsum[NBLK];                   // scan block sums
__device__ int2   g_epack[N_EDGES];               // (src, weight-bits) by dst
__device__ unsigned char g_flag[N_NODES];         // node appears in sel_idx

// ---------------------------------------------------------------------------
__global__ void clear_kernel() {
    int i = blockIdx.x * blockDim.x + threadIdx.x;
    if (i < N_NODES) { g_cnt[i] = 0; g_flag[i] = 0; }
}

// x (fp32) -> g_xh (fp16), float4 -> 4 halves per thread
__global__ void convert_kernel(const float4* __restrict__ x4) {
    int i = blockIdx.x * blockDim.x + threadIdx.x;
    const int n4 = N_NODES * D4;
    if (i < n4) {
        float4 v = __ldg(&x4[i]);
        __half2 h01 = __floats2half2_rn(v.x, v.y);
        __half2 h23 = __floats2half2_rn(v.z, v.w);
        uint2 packed;
        packed.x = *reinterpret_cast<unsigned int*>(&h01);
        packed.y = *reinterpret_cast<unsigned int*>(&h23);
        reinterpret_cast<uint2*>(g_xh)[i] = packed;
    }
}

__global__ void flag_kernel(const int* __restrict__ sel) {
    int i = blockIdx.x * blockDim.x + threadIdx.x;
    if (i < N_POOL) g_flag[sel[i]] = 1;
}

__global__ void hist_kernel(const int* __restrict__ dst) {
    int i = blockIdx.x * blockDim.x + threadIdx.x;
    if (i < N_EDGES) atomicAdd(&g_cnt[dst[i]], 1);
}

// Two-level shfl block scan
__global__ void __launch_bounds__(SCAN_B) scan1_kernel() {
    __shared__ int wsum[32];
    int i = blockIdx.x * SCAN_B + threadIdx.x;
    int v = (i < N_NODES) ? g_cnt[i] : 0;
    int lane = threadIdx.x & 31, w = threadIdx.x >> 5;
    int s = v;
    #pragma unroll
    for (int d = 1; d < 32; d <<= 1) {
        int u = __shfl_up_sync(0xffffffffu, s, d);
        if (lane >= d) s += u;
    }
    if (lane == 31) wsum[w] = s;
    __syncthreads();
    if (w == 0) {
        int ws = wsum[lane];
        #pragma unroll
        for (int d = 1; d < 32; d <<= 1) {
            int u = __shfl_up_sync(0xffffffffu, ws, d);
            if (lane >= d) ws += u;
        }
        wsum[lane] = ws;
    }
    __syncthreads();
    int incl = s + (w > 0 ? wsum[w - 1] : 0);
    if (i < N_NODES) g_off[i] = incl - v;          // exclusive within block
    if (threadIdx.x == SCAN_B - 1) g_bsum[blockIdx.x] = incl;
}

// Parallel warp scan over 98 block sums
__global__ void scan2_kernel() {
    __shared__ int wsum[4];
    int t = threadIdx.x;                // 128 threads
    int v = (t < NBLK) ? g_bsum[t] : 0;
    int lane = t & 31, w = t >> 5;
    int s = v;
    #pragma unroll
    for (int d = 1; d < 32; d <<= 1) {
        int u = __shfl_up_sync(0xffffffffu, s, d);
        if (lane >= d) s += u;
    }
    if (lane == 31) wsum[w] = s;
    __syncthreads();
    if (w == 0 && lane < 4) {
        int ws = wsum[lane];
        #pragma unroll
        for (int d = 1; d < 4; d <<= 1) {
            int u = __shfl_up_sync(0xfu, ws, d);
            if (lane >= d) ws += u;
        }
        wsum[lane] = ws;
    }
    __syncthreads();
    int incl = s + (w > 0 ? wsum[w - 1] : 0);
    if (t < NBLK) g_bsum[t] = incl - v;            // exclusive
}

__global__ void scan3_kernel() {
    int i = blockIdx.x * blockDim.x + threadIdx.x;
    if (i < N_NODES) {
        int o = g_off[i] + g_bsum[i / SCAN_B];
        g_off[i] = o;
        g_cur[i] = o;
    }
}

__global__ void reorder_kernel(const int* __restrict__ src,
                               const int* __restrict__ dst,
                               const float* __restrict__ ea) {
    int i = blockIdx.x * blockDim.x + threadIdx.x;
    if (i < N_EDGES) {
        int d   = dst[i];
        int pos = atomicAdd(&g_cur[d], 1);
        g_epack[pos] = make_int2(src[i], __float_as_int(ea[i]));  // one 8B store
    }
}

// ---------------------------------------------------------------------------
// Hop 1: fp16 gather, fp32 accumulate. One warp per dst node.
//   Y[n] = x[n] + sum_e half(x[src_e]) * w_e
// ---------------------------------------------------------------------------
__global__ void __launch_bounds__(256) hop1_half_kernel(
    const float4* __restrict__ base4,   // fp32 residual seed (x)
    float4* __restrict__ out4)          // Y
{
    int n    = (blockIdx.x * blockDim.x + threadIdx.x) >> 5;
    int lane = threadIdx.x & 31;
    if (n >= N_NODES) return;

    float4 acc = __ldg(&base4[(size_t)n * D4 + lane]);

    int s0 = __ldg(&g_off[n]);
    int c  = __ldg(&g_cnt[n]);

    const uint2* xh2 = reinterpret_cast<const uint2*>(g_xh);

    for (int b = 0; b < c; b += 32) {
        int idx = b + lane;
        int   s = 0;
        float w = 0.f;
        if (idx < c) {
            int2 e = __ldg(&g_epack[s0 + idx]);
            s = e.x;
            w = __int_as_float(e.y);
        }
        int m = min(32, c - b);
        #pragma unroll 4
        for (int j = 0; j < m; ++j) {
            int   ss = __shfl_sync(0xffffffffu, s, j);
            float ww = __shfl_sync(0xffffffffu, w, j);
            uint2 h = __ldg(&xh2[(size_t)ss * D4 + lane]);   // 4 halves
            __half2 h01 = *reinterpret_cast<__half2*>(&h.x);
            __half2 h23 = *reinterpret_cast<__half2*>(&h.y);
            float2 f01 = __half22float2(h01);
            float2 f23 = __half22float2(h23);
            acc.x += f01.x * ww;
            acc.y += f01.y * ww;
            acc.z += f23.x * ww;
            acc.w += f23.y * ww;
        }
    }
    out4[(size_t)n * D4 + lane] = acc;
}

// ---------------------------------------------------------------------------
// Hop 2: full fp32 gather (flagged nodes only).
//   Z[n] = Y[n] + sum_e Y[src_e] * w_e
// ---------------------------------------------------------------------------
__global__ void __launch_bounds__(256) hop2_kernel(
    const float4* __restrict__ Y4,
    float4* __restrict__ out4)
{
    int n    = (blockIdx.x * blockDim.x + threadIdx.x) >> 5;
    int lane = threadIdx.x & 31;
    if (n >= N_NODES) return;
    if (!g_flag[n]) return;

    float4 acc = __ldg(&Y4[(size_t)n * D4 + lane]);

    int s0 = __ldg(&g_off[n]);
    int c  = __ldg(&g_cnt[n]);

    for (int b = 0; b < c; b += 32) {
        int idx = b + lane;
        int   s = 0;
        float w = 0.f;
        if (idx < c) {
            int2 e = __ldg(&g_epack[s0 + idx]);
            s = e.x;
            w = __int_as_float(e.y);
        }
        int m = min(32, c - b);
        #pragma unroll 4
        for (int j = 0; j < m; ++j) {
            int   ss = __shfl_sync(0xffffffffu, s, j);
            float ww = __shfl_sync(0xffffffffu, w, j);
            float4 v = __ldg(&Y4[(size_t)ss * D4 + lane]);
            acc.x += v.x * ww;
            acc.y += v.y * ww;
            acc.z += v.z * ww;
            acc.w += v.w * ww;
        }
    }
    out4[(size_t)n * D4 + lane] = acc;
}

// ---------------------------------------------------------------------------
__global__ void __launch_bounds__(256) gather_kernel(
    const int* __restrict__ sel, float4* __restrict__ out4)
{
    int row  = (blockIdx.x * blockDim.x + threadIdx.x) >> 5;
    int lane = threadIdx.x & 31;
    if (row >= N_POOL) return;
    int s = __ldg(sel + row);
    const float4* z4 = reinterpret_cast<const float4*>(g_Z);
    out4[(size_t)row * D4 + lane] = __ldg(&z4[(size_t)s * D4 + lane]);
}

// ---------------------------------------------------------------------------
extern "C" void kernel_launch(void* const* d_in, const int* in_sizes, int n_in,
                              void* d_out, int out_size)
{
    const float* x    = (const float*)d_in[0];   // [N, 128] f32
    const float* ea   = (const float*)d_in[1];   // [E] f32
    const int*   eidx = (const int*)d_in[2];     // [2, E] int32
    const int*   sel  = (const int*)d_in[3];     // [N_pool] int32
    float* out = (float*)d_out;

    const int* src = eidx;            // row 0 (x_j sources)
    const int* dst = eidx + N_EDGES;  // row 1 (aggregation targets)

    float* Y; float* Z;
    cudaGetSymbolAddress((void**)&Y, g_Y);
    cudaGetSymbolAddress((void**)&Z, g_Z);
    const float4* x4 = reinterpret_cast<const float4*>(x);
    float4* Y4 = reinterpret_cast<float4*>(Y);
    float4* Z4 = reinterpret_cast<float4*>(Z);

    const int TB = 256;

    // CSR build (by dst) + selection flags + fp16 copy of x
    clear_kernel<<<(N_NODES + TB - 1) / TB, TB>>>();
    convert_kernel<<<(N_NODES * D4 + TB - 1) / TB, TB>>>(x4);
    hist_kernel<<<(N_EDGES + TB - 1) / TB, TB>>>(dst);
    flag_kernel<<<(N_POOL + TB - 1) / TB, TB>>>(sel);
    scan1_kernel<<<NBLK, SCAN_B>>>();
    scan2_kernel<<<1, 128>>>();
    scan3_kernel<<<(N_NODES + TB - 1) / TB, TB>>>();
    reorder_kernel<<<(N_EDGES + TB - 1) / TB, TB>>>(src, dst, ea);

    // hop 1 (all nodes, fp16 gather):  Y = x + A@x
    {
        int blocks = (N_NODES * 32 + TB - 1) / TB;
        hop1_half_kernel<<<blocks, TB>>>(x4, Y4);
    }
    // hop 2 (flagged only, fp32):      Z = Y + A@Y
    {
        int blocks = (N_NODES * 32 + TB - 1) / TB;
        hop2_kernel<<<blocks, TB>>>((const float4*)Y4, Z4);
    }
    // out = Z[sel]
    {
        int blocks = (N_POOL * 32 + TB - 1) / TB;
        gather_kernel<<<blocks, TB>>>(sel, (float4*)out);
    }
}

// round 8
// speedup vs baseline: 1.1447x; 1.1447x over previous
#include <cuda_runtime.h>
#include <cstdint>

#define N_NODES 100000
#define N_EDGES 1600000
#define D_FEAT  128
#define N_POOL  25000
#define D4      (D_FEAT / 4)          // 32 float4 per row -> one warp per row
#define SCAN_B  1024
#define NBLK    ((N_NODES + SCAN_B - 1) / SCAN_B)   // 98

// ---- scratch (__device__ globals; allocation is forbidden) ----------------
__device__ float g_Y[(size_t)N_NODES * D_FEAT];   // hop-1 result: x + agg1
__device__ int   g_cnt[N_NODES];                  // in-degree histogram
__device__ int   g_off[N_NODES];                  // CSR row offsets (exclusive)
__device__ int   g_cur[N_NODES];                  // write cursors for reorder
__device__ int   g_bsum[NBLK];                    // tile sums -> exclusive prefixes
__device__ int   g_done;                          // scan completion counter
__device__ int2  g_epack[N_EDGES];                // (src, weight-bits) sorted by dst

// ---------------------------------------------------------------------------
__global__ void clear_kernel() {
    int i = blockIdx.x * blockDim.x + threadIdx.x;
    if (i < N_NODES) g_cnt[i] = 0;
    if (i == 0) g_done = 0;
}

__global__ void hist_kernel(const int* __restrict__ dst) {
    int i = blockIdx.x * blockDim.x + threadIdx.x;
    if (i < N_EDGES) atomicAdd(&g_cnt[dst[i]], 1);
}

// ---------------------------------------------------------------------------
// Fused scan: each block scans its 1024-tile (two-level shfl), publishes its
// tile total; the LAST block to finish scans the 98 tile sums in-place
// (g_bsum becomes exclusive tile prefixes). scan3 then applies them.
// ---------------------------------------------------------------------------
__global__ void __launch_bounds__(SCAN_B) scan_fused_kernel() {
    __shared__ int wsum[32];
    __shared__ int is_last;
    int i = blockIdx.x * SCAN_B + threadIdx.x;
    int v = (i < N_NODES) ? g_cnt[i] : 0;
    int lane = threadIdx.x & 31, w = threadIdx.x >> 5;
    int s = v;
    #pragma unroll
    for (int d = 1; d < 32; d <<= 1) {
        int u = __shfl_up_sync(0xffffffffu, s, d);
        if (lane >= d) s += u;
    }
    if (lane == 31) wsum[w] = s;
    __syncthreads();
    if (w == 0) {
        int ws = wsum[lane];
        #pragma unroll
        for (int d = 1; d < 32; d <<= 1) {
            int u = __shfl_up_sync(0xffffffffu, ws, d);
            if (lane >= d) ws += u;
        }
        wsum[lane] = ws;
    }
    __syncthreads();
    int incl = s + (w > 0 ? wsum[w - 1] : 0);
    if (i < N_NODES) g_off[i] = incl - v;           // exclusive within tile
    if (threadIdx.x == SCAN_B - 1) g_bsum[blockIdx.x] = incl;  // tile total

    // last-block-done: scan the tile sums
    __threadfence();
    if (threadIdx.x == 0)
        is_last = (atomicAdd(&g_done, 1) == gridDim.x - 1);
    __syncthreads();
    if (is_last) {
        __shared__ int wsum2[4];
        int t = threadIdx.x;                         // use first 128 threads
        int bv = 0;
        if (t < NBLK) {
            const volatile int* bs = g_bsum;         // other SMs wrote these
            bv = bs[t];
        }
        if (t < 128) {
            int s2 = bv;
            #pragma unroll
            for (int d = 1; d < 32; d <<= 1) {
                int u = __shfl_up_sync(0xffffffffu, s2, d);
                if (lane >= d) s2 += u;
            }
            if (lane == 31) wsum2[w] = s2;
        }
        __syncthreads();
        if (t < 32) {
            int ws = (lane < 4) ? wsum2[lane] : 0;
            #pragma unroll
            for (int d = 1; d < 4; d <<= 1) {
                int u = __shfl_up_sync(0xffffffffu, ws, d);
                if (lane >= d) ws += u;
            }
            if (lane < 4) wsum2[lane] = ws;
        }
        __syncthreads();
        if (t < NBLK) {
            int s2 = bv;
            #pragma unroll
            for (int d = 1; d < 32; d <<= 1) {
                int u = __shfl_up_sync(0xffffffffu, s2, d);
                if (lane >= d) s2 += u;
            }
            int incl2 = s2 + (w > 0 ? wsum2[w - 1] : 0);
            g_bsum[t] = incl2 - bv;                  // exclusive tile prefix
        }
    }
}

__global__ void scan3_kernel() {
    int i = blockIdx.x * blockDim.x + threadIdx.x;
    if (i < N_NODES) {
        int o = g_off[i] + g_bsum[i / SCAN_B];
        g_off[i] = o;
        g_cur[i] = o;
    }
}

__global__ void reorder_kernel(const int* __restrict__ src,
                               const int* __restrict__ dst,
                               const float* __restrict__ ea) {
    int i = blockIdx.x * blockDim.x + threadIdx.x;
    if (i < N_EDGES) {
        int d   = dst[i];
        int pos = atomicAdd(&g_cur[d], 1);
        g_epack[pos] = make_int2(src[i], __float_as_int(ea[i]));  // one 8B store
    }
}

// ---------------------------------------------------------------------------
// Hop 1 (all nodes): Y[n] = x[n] + sum_e x[src_e] * w_e
// One warp per dst node, one float4 per lane, fp32 throughout.
// ---------------------------------------------------------------------------
__global__ void __launch_bounds__(256) hop1_kernel(
    const float4* __restrict__ x4, float4* __restrict__ Y4)
{
    int n    = (blockIdx.x * blockDim.x + threadIdx.x) >> 5;
    int lane = threadIdx.x & 31;
    if (n >= N_NODES) return;

    float4 acc = __ldg(&x4[(size_t)n * D4 + lane]);
    int s0 = __ldg(&g_off[n]);
    int c  = __ldg(&g_cnt[n]);

    for (int b = 0; b < c; b += 32) {
        int idx = b + lane;
        int   s = 0;
        float w = 0.f;
        if (idx < c) {
            int2 e = __ldg(&g_epack[s0 + idx]);
            s = e.x;
            w = __int_as_float(e.y);
        }
        int m = min(32, c - b);
        #pragma unroll 8
        for (int j = 0; j < m; ++j) {
            int   ss = __shfl_sync(0xffffffffu, s, j);
            float ww = __shfl_sync(0xffffffffu, w, j);
            float4 v = __ldg(&x4[(size_t)ss * D4 + lane]);
            acc.x += v.x * ww;
            acc.y += v.y * ww;
            acc.z += v.z * ww;
            acc.w += v.w * ww;
        }
    }
    Y4[(size_t)n * D4 + lane] = acc;
}

// ---------------------------------------------------------------------------
// Hop 2 fused with selection gather: one warp per OUTPUT row.
//   out[i] = Y[sel[i]] + sum_{e in CSR(sel[i])} Y[src_e] * w_e
// Duplicate sel entries are simply recomputed (~12% extra edges).
// ---------------------------------------------------------------------------
__global__ void __launch_bounds__(256) hop2_direct_kernel(
    const int* __restrict__ sel,
    const float4* __restrict__ Y4,
    float4* __restrict__ out4)
{
    int row  = (blockIdx.x * blockDim.x + threadIdx.x) >> 5;
    int lane = threadIdx.x & 31;
    if (row >= N_POOL) return;

    int n = __ldg(sel + row);
    float4 acc = __ldg(&Y4[(size_t)n * D4 + lane]);
    int s0 = __ldg(&g_off[n]);
    int c  = __ldg(&g_cnt[n]);

    for (int b = 0; b < c; b += 32) {
        int idx = b + lane;
        int   s = 0;
        float w = 0.f;
        if (idx < c) {
            int2 e = __ldg(&g_epack[s0 + idx]);
            s = e.x;
            w = __int_as_float(e.y);
        }
        int m = min(32, c - b);
        #pragma unroll 8
        for (int j = 0; j < m; ++j) {
            int   ss = __shfl_sync(0xffffffffu, s, j);
            float ww = __shfl_sync(0xffffffffu, w, j);
            float4 v = __ldg(&Y4[(size_t)ss * D4 + lane]);
            acc.x += v.x * ww;
            acc.y += v.y * ww;
            acc.z += v.z * ww;
            acc.w += v.w * ww;
        }
    }
    out4[(size_t)row * D4 + lane] = acc;
}

// ---------------------------------------------------------------------------
extern "C" void kernel_launch(void* const* d_in, const int* in_sizes, int n_in,
                              void* d_out, int out_size)
{
    const float* x    = (const float*)d_in[0];   // [N, 128] f32
    const float* ea   = (const float*)d_in[1];   // [E] f32
    const int*   eidx = (const int*)d_in[2];     // [2, E] int32
    const int*   sel  = (const int*)d_in[3];     // [N_pool] int32
    float* out = (float*)d_out;

    const int* src = eidx;            // row 0 (x_j sources)
    const int* dst = eidx + N_EDGES;  // row 1 (aggregation targets)

    float* Y;
    cudaGetSymbolAddress((void**)&Y, g_Y);
    const float4* x4 = reinterpret_cast<const float4*>(x);
    float4* Y4 = reinterpret_cast<float4*>(Y);

    const int TB = 256;

    // CSR build (by dst): clear -> hist -> fused scan -> apply -> reorder
    clear_kernel<<<(N_NODES + TB - 1) / TB, TB>>>();
    hist_kernel<<<(N_EDGES + TB - 1) / TB, TB>>>(dst);
    scan_fused_kernel<<<NBLK, SCAN_B>>>();
    scan3_kernel<<<(N_NODES + TB - 1) / TB, TB>>>();
    reorder_kernel<<<(N_EDGES + TB - 1) / TB, TB>>>(src, dst, ea);

    // hop 1 (all nodes):  Y = x + A@x
    hop1_kernel<<<(N_NODES * 32 + TB - 1) / TB, TB>>>(x4, Y4);

    // hop 2 fused with output gather: out[i] = (Y + A@Y)[sel[i]]
    hop2_direct_kernel<<<(N_POOL * 32 + TB - 1) / TB, TB>>>(
        sel, (const float4*)Y4, (float4*)out);
}

// round 9
// speedup vs baseline: 1.1982x; 1.0467x over previous
#include <cuda_runtime.h>
#include <cstdint>

#define N_NODES 100000
#define N_EDGES 1600000
#define D_FEAT  128
#define N_POOL  25000
#define D4      (D_FEAT / 4)          // 32 float4 per row -> one warp per row
#define SCAN_B  1024
#define NBLK    ((N_NODES + SCAN_B - 1) / SCAN_B)   // 98

// ---- scratch (__device__ globals; zero-initialized at load) ---------------
__device__ float g_Y[(size_t)N_NODES * D_FEAT];   // hop-1 result: x + agg1
__device__ int   g_cnt[N_NODES];                  // histogram (self-cleared by scan)
__device__ int   g_off[N_NODES + 1];              // within-tile exclusive offsets (+sentinel)
__device__ int   g_cur[N_NODES];                  // within-tile write cursors
__device__ int   g_bsum[NBLK];                    // exclusive tile prefixes
__device__ int   g_done;                          // scan completion counter (self-reset)
__device__ int2  g_epack[N_EDGES];                // (src, weight-bits) sorted by dst

// ---------------------------------------------------------------------------
// Histogram: 4 edges per thread (int4 loads).
// ---------------------------------------------------------------------------
__global__ void hist_kernel(const int4* __restrict__ dst4) {
    int i = blockIdx.x * blockDim.x + threadIdx.x;
    if (i < N_EDGES / 4) {
        int4 d = __ldg(&dst4[i]);
        atomicAdd(&g_cnt[d.x], 1);
        atomicAdd(&g_cnt[d.y], 1);
        atomicAdd(&g_cnt[d.z], 1);
        atomicAdd(&g_cnt[d.w], 1);
    }
}

// ---------------------------------------------------------------------------
// Fused scan:
//  - each block: two-level shfl scan of its 1024-tile; writes WITHIN-TILE
//    exclusive offsets to g_off and g_cur, zeroes g_cnt (last reader),
//    publishes tile total to g_bsum.
//  - last block to finish: converts g_bsum to exclusive tile prefixes
//    in place, resets g_done for the next replay.
//  Global offset of node n is g_off[n] + g_bsum[n >> 10] (applied lazily).
// ---------------------------------------------------------------------------
__global__ void __launch_bounds__(SCAN_B) scan_fused_kernel() {
    __shared__ int wsum[32];
    __shared__ int is_last;
    int i = blockIdx.x * SCAN_B + threadIdx.x;
    int v = (i < N_NODES) ? g_cnt[i] : 0;
    if (i < N_NODES) g_cnt[i] = 0;                 // self-clear for next replay
    int lane = threadIdx.x & 31, w = threadIdx.x >> 5;
    int s = v;
    #pragma unroll
    for (int d = 1; d < 32; d <<= 1) {
        int u = __shfl_up_sync(0xffffffffu, s, d);
        if (lane >= d) s += u;
    }
    if (lane == 31) wsum[w] = s;
    __syncthreads();
    if (w == 0) {
        int ws = wsum[lane];
        #pragma unroll
        for (int d = 1; d < 32; d <<= 1) {
            int u = __shfl_up_sync(0xffffffffu, ws, d);
            if (lane >= d) ws += u;
        }
        wsum[lane] = ws;
    }
    __syncthreads();
    int incl = s + (w > 0 ? wsum[w - 1] : 0);
    int excl = incl - v;
    if (i <= N_NODES) g_off[i] = excl;             // includes sentinel at i==N
    if (i < N_NODES)  g_cur[i] = excl;
    if (threadIdx.x == SCAN_B - 1) g_bsum[blockIdx.x] = incl;  // tile total

    // last-block-done: scan the 98 tile sums -> exclusive tile prefixes
    __threadfence();
    if (threadIdx.x == 0)
        is_last = (atomicAdd(&g_done, 1) == gridDim.x - 1);
    __syncthreads();
    if (is_last) {
        __shared__ int wsum2[4];
        int t = threadIdx.x;
        int bv = 0;
        if (t < NBLK) {
            const volatile int* bs = g_bsum;       // other SMs wrote these
            bv = bs[t];
        }
        if (t < 128) {
            int s2 = bv;
            #pragma unroll
            for (int d = 1; d < 32; d <<= 1) {
                int u = __shfl_up_sync(0xffffffffu, s2, d);
                if (lane >= d) s2 += u;
            }
            if (lane == 31) wsum2[w] = s2;
        }
        __syncthreads();
        if (t < 32) {
            int ws = (lane < 4) ? wsum2[lane] : 0;
            #pragma unroll
            for (int d = 1; d < 4; d <<= 1) {
                int u = __shfl_up_sync(0xffffffffu, ws, d);
                if (lane >= d) ws += u;
            }
            if (lane < 4) wsum2[lane] = ws;
        }
        __syncthreads();
        if (t < NBLK) {
            int s2 = bv;
            #pragma unroll
            for (int d = 1; d < 32; d <<= 1) {
                int u = __shfl_up_sync(0xffffffffu, s2, d);
                if (lane >= d) s2 += u;
            }
            int incl2 = s2 + (w > 0 ? wsum2[w - 1] : 0);
            g_bsum[t] = incl2 - bv;                // exclusive tile prefix
        }
        if (threadIdx.x == 0) g_done = 0;          // self-reset for next replay
    }
}

// ---------------------------------------------------------------------------
__global__ void reorder_kernel(const int* __restrict__ src,
                               const int* __restrict__ dst,
                               const float* __restrict__ ea) {
    int i = blockIdx.x * blockDim.x + threadIdx.x;
    if (i < N_EDGES) {
        int d   = dst[i];
        int pos = atomicAdd(&g_cur[d], 1) + __ldg(&g_bsum[d >> 10]);
        g_epack[pos] = make_int2(src[i], __float_as_int(ea[i]));
    }
}

// ---------------------------------------------------------------------------
// Hop 1 (all nodes): Y[n] = x[n] + sum_e x[src_e] * w_e
// One warp per dst node, one float4 per lane, fp32 throughout.
// ---------------------------------------------------------------------------
__global__ void __launch_bounds__(256) hop1_kernel(
    const float4* __restrict__ x4, float4* __restrict__ Y4)
{
    int n    = (blockIdx.x * blockDim.x + threadIdx.x) >> 5;
    int lane = threadIdx.x & 31;
    if (n >= N_NODES) return;

    float4 acc = __ldg(&x4[(size_t)n * D4 + lane]);
    int s0 = __ldg(&g_off[n])     + __ldg(&g_bsum[n >> 10]);
    int e0 = __ldg(&g_off[n + 1]) + __ldg(&g_bsum[(n + 1) >> 10]);
    int c  = e0 - s0;

    for (int b = 0; b < c; b += 32) {
        int idx = b + lane;
        int   s = 0;
        float w = 0.f;
        if (idx < c) {
            int2 e = __ldg(&g_epack[s0 + idx]);
            s = e.x;
            w = __int_as_float(e.y);
        }
        int m = min(32, c - b);
        #pragma unroll 8
        for (int j = 0; j < m; ++j) {
            int   ss = __shfl_sync(0xffffffffu, s, j);
            float ww = __shfl_sync(0xffffffffu, w, j);
            float4 v = __ldg(&x4[(size_t)ss * D4 + lane]);
            acc.x += v.x * ww;
            acc.y += v.y * ww;
            acc.z += v.z * ww;
            acc.w += v.w * ww;
        }
    }
    Y4[(size_t)n * D4 + lane] = acc;
}

// ---------------------------------------------------------------------------
// Hop 2 fused with selection gather: one warp per OUTPUT row.
//   out[i] = Y[sel[i]] + sum_{e in CSR(sel[i])} Y[src_e] * w_e
// ---------------------------------------------------------------------------
__global__ void __launch_bounds__(256) hop2_direct_kernel(
    const int* __restrict__ sel,
    const float4* __restrict__ Y4,
    float4* __restrict__ out4)
{
    int row  = (blockIdx.x * blockDim.x + threadIdx.x) >> 5;
    int lane = threadIdx.x & 31;
    if (row >= N_POOL) return;

    int n = __ldg(sel + row);
    float4 acc = __ldg(&Y4[(size_t)n * D4 + lane]);
    int s0 = __ldg(&g_off[n])     + __ldg(&g_bsum[n >> 10]);
    int e0 = __ldg(&g_off[n + 1]) + __ldg(&g_bsum[(n + 1) >> 10]);
    int c  = e0 - s0;

    for (int b = 0; b < c; b += 32) {
        int idx = b + lane;
        int   s = 0;
        float w = 0.f;
        if (idx < c) {
            int2 e = __ldg(&g_epack[s0 + idx]);
            s = e.x;
            w = __int_as_float(e.y);
        }
        int m = min(32, c - b);
        #pragma unroll 8
        for (int j = 0; j < m; ++j) {
            int   ss = __shfl_sync(0xffffffffu, s, j);
            float ww = __shfl_sync(0xffffffffu, w, j);
            float4 v = __ldg(&Y4[(size_t)ss * D4 + lane]);
            acc.x += v.x * ww;
            acc.y += v.y * ww;
            acc.z += v.z * ww;
            acc.w += v.w * ww;
        }
    }
    out4[(size_t)row * D4 + lane] = acc;
}

// ---------------------------------------------------------------------------
extern "C" void kernel_launch(void* const* d_in, const int* in_sizes, int n_in,
                              void* d_out, int out_size)
{
    const float* x    = (const float*)d_in[0];   // [N, 128] f32
    const float* ea   = (const float*)d_in[1];   // [E] f32
    const int*   eidx = (const int*)d_in[2];     // [2, E] int32
    const int*   sel  = (const int*)d_in[3];     // [N_pool] int32
    float* out = (float*)d_out;

    const int* src = eidx;            // row 0 (x_j sources)
    const int* dst = eidx + N_EDGES;  // row 1 (aggregation targets)

    float* Y;
    cudaGetSymbolAddress((void**)&Y, g_Y);
    const float4* x4 = reinterpret_cast<const float4*>(x);
    float4* Y4 = reinterpret_cast<float4*>(Y);

    const int TB = 256;

    // CSR build: hist -> fused scan (self-cleaning) -> reorder
    hist_kernel<<<(N_EDGES / 4 + TB - 1) / TB, TB>>>(
        reinterpret_cast<const int4*>(dst));
    scan_fused_kernel<<<NBLK, SCAN_B>>>();
    reorder_kernel<<<(N_EDGES + TB - 1) / TB, TB>>>(src, dst, ea);

    // hop 1 (all nodes):  Y = x + A@x      (4th launch -> ncu-profiled slot)
    hop1_kernel<<<(N_NODES * 32 + TB - 1) / TB, TB>>>(x4, Y4);

    // hop 2 fused with output gather: out[i] = (Y + A@Y)[sel[i]]
    hop2_direct_kernel<<<(N_POOL * 32 + TB - 1) / TB, TB>>>(
        sel, (const float4*)Y4, (float4*)out);
}

// round 10
// speedup vs baseline: 1.2886x; 1.0755x over previous
#include <cuda_runtime.h>
#include <cuda_fp16.h>
#include <cstdint>

#define N_NODES 100000
#define N_EDGES 1600000
#define D_FEAT  128
#define N_POOL  25000
#define D4      (D_FEAT / 4)          // 32 float4 per row -> one warp per row
#define N4      (N_NODES * D4)        // 3.2M float4 in x
#define SCAN_B  1024
#define NBLK    ((N_NODES + SCAN_B - 1) / SCAN_B)   // 98

// ---- scratch (__device__ globals; zero-initialized at load) ---------------
__device__ float  g_Y[(size_t)N_NODES * D_FEAT];  // hop-1 result: x + agg1
__device__ __half g_xh[(size_t)N_NODES * D_FEAT]; // fp16 copy of x (hop-1 gather)
__device__ int    g_cnt[N_NODES];                 // histogram (self-cleared by scan)
__device__ int    g_off[N_NODES + 1];             // within-tile excl offsets (+sentinel)
__device__ int    g_cur[N_NODES];                 // within-tile write cursors
__device__ int    g_bsum[NBLK];                   // exclusive tile prefixes
__device__ int    g_done;                         // scan completion counter (self-reset)
__device__ int2   g_epack[N_EDGES];               // (src, weight-bits) sorted by dst

// ---------------------------------------------------------------------------
// Fused histogram + fp16 convert. Thread i:
//   - i < N_EDGES/4 : histogram 4 dst ids (int4 load)
//   - i < N4        : convert one float4 of x -> 4 halves (uint2 store)
// Independent roles; grid sized for the larger (N4).
// ---------------------------------------------------------------------------
__global__ void hist_convert_kernel(const int4* __restrict__ dst4,
                                    const float4* __restrict__ x4) {
    int i = blockIdx.x * blockDim.x + threadIdx.x;
    if (i < N_EDGES / 4) {
        int4 d = __ldg(&dst4[i]);
        atomicAdd(&g_cnt[d.x], 1);
        atomicAdd(&g_cnt[d.y], 1);
        atomicAdd(&g_cnt[d.z], 1);
        atomicAdd(&g_cnt[d.w], 1);
    }
    if (i < N4) {
        float4 v = __ldg(&x4[i]);
        __half2 h01 = __floats2half2_rn(v.x, v.y);
        __half2 h23 = __floats2half2_rn(v.z, v.w);
        uint2 p;
        p.x = *reinterpret_cast<unsigned int*>(&h01);
        p.y = *reinterpret_cast<unsigned int*>(&h23);
        reinterpret_cast<uint2*>(g_xh)[i] = p;
    }
}

// ---------------------------------------------------------------------------
// Fused scan (see R8): within-tile offsets + lazy tile prefixes; self-cleans
// g_cnt and g_done for graph replay.
// ---------------------------------------------------------------------------
__global__ void __launch_bounds__(SCAN_B) scan_fused_kernel() {
    __shared__ int wsum[32];
    __shared__ int is_last;
    int i = blockIdx.x * SCAN_B + threadIdx.x;
    int v = (i < N_NODES) ? g_cnt[i] : 0;
    if (i < N_NODES) g_cnt[i] = 0;                 // self-clear for next replay
    int lane = threadIdx.x & 31, w = threadIdx.x >> 5;
    int s = v;
    #pragma unroll
    for (int d = 1; d < 32; d <<= 1) {
        int u = __shfl_up_sync(0xffffffffu, s, d);
        if (lane >= d) s += u;
    }
    if (lane == 31) wsum[w] = s;
    __syncthreads();
    if (w == 0) {
        int ws = wsum[lane];
        #pragma unroll
        for (int d = 1; d < 32; d <<= 1) {
            int u = __shfl_up_sync(0xffffffffu, ws, d);
            if (lane >= d) ws += u;
        }
        wsum[lane] = ws;
    }
    __syncthreads();
    int incl = s + (w > 0 ? wsum[w - 1] : 0);
    int excl = incl - v;
    if (i <= N_NODES) g_off[i] = excl;             // includes sentinel at i==N
    if (i < N_NODES)  g_cur[i] = excl;
    if (threadIdx.x == SCAN_B - 1) g_bsum[blockIdx.x] = incl;  // tile total

    __threadfence();
    if (threadIdx.x == 0)
        is_last = (atomicAdd(&g_done, 1) == gridDim.x - 1);
    __syncthreads();
    if (is_last) {
        __shared__ int wsum2[4];
        int t = threadIdx.x;
        int bv = 0;
        if (t < NBLK) {
            const volatile int* bs = g_bsum;
            bv = bs[t];
        }
        if (t < 128) {
            int s2 = bv;
            #pragma unroll
            for (int d = 1; d < 32; d <<= 1) {
                int u = __shfl_up_sync(0xffffffffu, s2, d);
                if (lane >= d) s2 += u;
            }
            if (lane == 31) wsum2[w] = s2;
        }
        __syncthreads();
        if (t < 32) {
            int ws = (lane < 4) ? wsum2[lane] : 0;
            #pragma unroll
            for (int d = 1; d < 4; d <<= 1) {
                int u = __shfl_up_sync(0xffffffffu, ws, d);
                if (lane >= d) ws += u;
            }
            if (lane < 4) wsum2[lane] = ws;
        }
        __syncthreads();
        if (t < NBLK) {
            int s2 = bv;
            #pragma unroll
            for (int d = 1; d < 32; d <<= 1) {
                int u = __shfl_up_sync(0xffffffffu, s2, d);
                if (lane >= d) s2 += u;
            }
            int incl2 = s2 + (w > 0 ? wsum2[w - 1] : 0);
            g_bsum[t] = incl2 - bv;                // exclusive tile prefix
        }
        if (threadIdx.x == 0) g_done = 0;          // self-reset for next replay
    }
}

// ---------------------------------------------------------------------------
__global__ void reorder_kernel(const int* __restrict__ src,
                               const int* __restrict__ dst,
                               const float* __restrict__ ea) {
    int i = blockIdx.x * blockDim.x + threadIdx.x;
    if (i < N_EDGES) {
        int d   = dst[i];
        int pos = atomicAdd(&g_cur[d], 1) + __ldg(&g_bsum[d >> 10]);
        g_epack[pos] = make_int2(src[i], __float_as_int(ea[i]));
    }
}

// ---------------------------------------------------------------------------
// Hop 1 (all nodes): Y[n] = x[n] + sum_e half(x[src_e]) * w_e
// One warp per dst node. Edge records read as UNIFORM broadcast loads
// (1 L1 wavefront each, no SHFL); gathered rows are fp16 (2 wavefronts).
// ---------------------------------------------------------------------------
__global__ void __launch_bounds__(256) hop1_kernel(
    const float4* __restrict__ x4, float4* __restrict__ Y4)
{
    int n    = (blockIdx.x * blockDim.x + threadIdx.x) >> 5;
    int lane = threadIdx.x & 31;
    if (n >= N_NODES) return;

    float4 acc = __ldg(&x4[(size_t)n * D4 + lane]);
    int s0 = __ldg(&g_off[n])     + __ldg(&g_bsum[n >> 10]);
    int e0 = __ldg(&g_off[n + 1]) + __ldg(&g_bsum[(n + 1) >> 10]);

    const uint2* xh2 = reinterpret_cast<const uint2*>(g_xh);

    #pragma unroll 4
    for (int j = s0; j < e0; ++j) {
        int2 e = __ldg(&g_epack[j]);               // uniform -> broadcast, 1 wf
        float w = __int_as_float(e.y);
        uint2 h = __ldg(&xh2[(size_t)e.x * D4 + lane]);  // fp16 row, 2 wf
        __half2 h01 = *reinterpret_cast<__half2*>(&h.x);
        __half2 h23 = *reinterpret_cast<__half2*>(&h.y);
        float2 f01 = __half22float2(h01);
        float2 f23 = __half22float2(h23);
        acc.x += f01.x * w;
        acc.y += f01.y * w;
        acc.z += f23.x * w;
        acc.w += f23.y * w;
    }
    Y4[(size_t)n * D4 + lane] = acc;
}

// ---------------------------------------------------------------------------
// Hop 2 fused with selection gather (fp32 throughout): one warp per OUTPUT row.
//   out[i] = Y[sel[i]] + sum_{e in CSR(sel[i])} Y[src_e] * w_e
// ---------------------------------------------------------------------------
__global__ void __launch_bounds__(256) hop2_direct_kernel(
    const int* __restrict__ sel,
    const float4* __restrict__ Y4,
    float4* __restrict__ out4)
{
    int row  = (blockIdx.x * blockDim.x + threadIdx.x) >> 5;
    int lane = threadIdx.x & 31;
    if (row >= N_POOL) return;

    int n = __ldg(sel + row);
    float4 acc = __ldg(&Y4[(size_t)n * D4 + lane]);
    int s0 = __ldg(&g_off[n])     + __ldg(&g_bsum[n >> 10]);
    int e0 = __ldg(&g_off[n + 1]) + __ldg(&g_bsum[(n + 1) >> 10]);

    #pragma unroll 4
    for (int j = s0; j < e0; ++j) {
        int2 e = __ldg(&g_epack[j]);               // uniform broadcast
        float w = __int_as_float(e.y);
        float4 v = __ldg(&Y4[(size_t)e.x * D4 + lane]);
        acc.x += v.x * w;
        acc.y += v.y * w;
        acc.z += v.z * w;
        acc.w += v.w * w;
    }
    out4[(size_t)row * D4 + lane] = acc;
}

// ---------------------------------------------------------------------------
extern "C" void kernel_launch(void* const* d_in, const int* in_sizes, int n_in,
                              void* d_out, int out_size)
{
    const float* x    = (const float*)d_in[0];   // [N, 128] f32
    const float* ea   = (const float*)d_in[1];   // [E] f32
    const int*   eidx = (const int*)d_in[2];     // [2, E] int32
    const int*   sel  = (const int*)d_in[3];     // [N_pool] int32
    float* out = (float*)d_out;

    const int* src = eidx;            // row 0 (x_j sources)
    const int* dst = eidx + N_EDGES;  // row 1 (aggregation targets)

    float* Y;
    cudaGetSymbolAddress((void**)&Y, g_Y);
    const float4* x4 = reinterpret_cast<const float4*>(x);
    float4* Y4 = reinterpret_cast<float4*>(Y);

    const int TB = 256;

    // CSR build + fp16 convert: (hist|convert) -> fused scan -> reorder
    hist_convert_kernel<<<(N4 + TB - 1) / TB, TB>>>(
        reinterpret_cast<const int4*>(dst), x4);
    scan_fused_kernel<<<NBLK, SCAN_B>>>();
    reorder_kernel<<<(N_EDGES + TB - 1) / TB, TB>>>(src, dst, ea);

    // hop 1 (all nodes, fp16 gather):  Y = x + A@x   (4th launch -> profiled)
    hop1_kernel<<<(N_NODES * 32 + TB - 1) / TB, TB>>>(x4, Y4);

    // hop 2 fused with output gather (fp32): out[i] = (Y + A@Y)[sel[i]]
    hop2_direct_kernel<<<(N_POOL * 32 + TB - 1) / TB, TB>>>(
        sel, (const float4*)Y4, (float4*)out);
}

// round 12
// speedup vs baseline: 1.4053x; 1.0906x over previous
#include <cuda_runtime.h>
#include <cuda_fp16.h>
#include <cstdint>

#define N_NODES 100000
#define N_EDGES 1600000
#define D_FEAT  128
#define N_POOL  25000
#define D4      (D_FEAT / 4)          // 32 float4 per fp32 row
#define N4      (N_NODES * D4)        // 3.2M float4 in x
#define SCAN_B  1024
#define NBLK    ((N_NODES + SCAN_B - 1) / SCAN_B)   // 98

// ---- scratch (__device__ globals; zero-initialized at load) ---------------
__device__ __half g_xh[(size_t)N_NODES * D_FEAT]; // fp16 copy of x  (hop-1 gather)
__device__ __half g_Yh[(size_t)N_NODES * D_FEAT]; // fp16 hop-1 out  (hop-2 gather)
__device__ int    g_cnt[N_NODES];                 // histogram (self-cleared by scan)
__device__ int    g_off[N_NODES + 1];             // within-tile excl offsets (+sentinel)
__device__ int    g_cur[N_NODES];                 // within-tile write cursors
__device__ int    g_bsum[NBLK];                   // exclusive tile prefixes
__device__ int    g_done;                         // scan completion counter (self-reset)
__device__ int2   g_epack[N_EDGES];               // (src*32, weight-bits) sorted by dst

// ---------------------------------------------------------------------------
// Fused histogram + fp16 convert (independent roles in one launch).
// ---------------------------------------------------------------------------
__global__ void hist_convert_kernel(const int4* __restrict__ dst4,
                                    const float4* __restrict__ x4) {
    int i = blockIdx.x * blockDim.x + threadIdx.x;
    if (i < N_EDGES / 4) {
        int4 d = __ldg(&dst4[i]);
        atomicAdd(&g_cnt[d.x], 1);
        atomicAdd(&g_cnt[d.y], 1);
        atomicAdd(&g_cnt[d.z], 1);
        atomicAdd(&g_cnt[d.w], 1);
    }
    if (i < N4) {
        float4 v = __ldg(&x4[i]);
        __half2 h01 = __floats2half2_rn(v.x, v.y);
        __half2 h23 = __floats2half2_rn(v.z, v.w);
        uint2 p;
        p.x = *reinterpret_cast<unsigned int*>(&h01);
        p.y = *reinterpret_cast<unsigned int*>(&h23);
        reinterpret_cast<uint2*>(g_xh)[i] = p;
    }
}

// ---------------------------------------------------------------------------
// Fused scan: within-tile offsets + lazy tile prefixes; self-cleans g_cnt and
// g_done for graph replay. Global offset of n = g_off[n] + g_bsum[n >> 10].
// ---------------------------------------------------------------------------
__global__ void __launch_bounds__(SCAN_B) scan_fused_kernel() {
    __shared__ int wsum[32];
    __shared__ int is_last;
    int i = blockIdx.x * SCAN_B + threadIdx.x;
    int v = (i < N_NODES) ? g_cnt[i] : 0;
    if (i < N_NODES) g_cnt[i] = 0;                 // self-clear for next replay
    int lane = threadIdx.x & 31, w = threadIdx.x >> 5;
    int s = v;
    #pragma unroll
    for (int d = 1; d < 32; d <<= 1) {
        int u = __shfl_up_sync(0xffffffffu, s, d);
        if (lane >= d) s += u;
    }
    if (lane == 31) wsum[w] = s;
    __syncthreads();
    if (w == 0) {
        int ws = wsum[lane];
        #pragma unroll
        for (int d = 1; d < 32; d <<= 1) {
            int u = __shfl_up_sync(0xffffffffu, ws, d);
            if (lane >= d) ws += u;
        }
        wsum[lane] = ws;
    }
    __syncthreads();
    int incl = s + (w > 0 ? wsum[w - 1] : 0);
    int excl = incl - v;
    if (i <= N_NODES) g_off[i] = excl;             // includes sentinel at i==N
    if (i < N_NODES)  g_cur[i] = excl;
    if (threadIdx.x == SCAN_B - 1) g_bsum[blockIdx.x] = incl;  // tile total

    __threadfence();
    if (threadIdx.x == 0)
        is_last = (atomicAdd(&g_done, 1) == gridDim.x - 1);
    __syncthreads();
    if (is_last) {
        __shared__ int wsum2[4];
        int t = threadIdx.x;
        int bv = 0;
        if (t < NBLK) {
            const volatile int* bs = g_bsum;
            bv = bs[t];
        }
        if (t < 128) {
            int s2 = bv;
            #pragma unroll
            for (int d = 1; d < 32; d <<= 1) {
                int u = __shfl_up_sync(0xffffffffu, s2, d);
                if (lane >= d) s2 += u;
            }
            if (lane == 31) wsum2[w] = s2;
        }
        __syncthreads();
        if (t < 32) {
            int ws = (lane < 4) ? wsum2[lane] : 0;
            #pragma unroll
            for (int d = 1; d < 4; d <<= 1) {
                int u = __shfl_up_sync(0xffffffffu, ws, d);
                if (lane >= d) ws += u;
            }
            if (lane < 4) wsum2[lane] = ws;
        }
        __syncthreads();
        if (t < NBLK) {
            int s2 = bv;
            #pragma unroll
            for (int d = 1; d < 32; d <<= 1) {
                int u = __shfl_up_sync(0xffffffffu, s2, d);
                if (lane >= d) s2 += u;
            }
            int incl2 = s2 + (w > 0 ? wsum2[w - 1] : 0);
            g_bsum[t] = incl2 - bv;                // exclusive tile prefix
        }
        if (threadIdx.x == 0) g_done = 0;          // self-reset for next replay
    }
}

// ---------------------------------------------------------------------------
// Reorder: edge record = (src * 32, weight-bits) — src pre-scaled to the
// uint2-row base so the hops avoid a per-edge IMAD.
// ---------------------------------------------------------------------------
__global__ void reorder_kernel(const int* __restrict__ src,
                               const int* __restrict__ dst,
                               const float* __restrict__ ea) {
    int i = blockIdx.x * blockDim.x + threadIdx.x;
    if (i < N_EDGES) {
        int d   = dst[i];
        int pos = atomicAdd(&g_cur[d], 1) + __ldg(&g_bsum[d >> 10]);
        g_epack[pos] = make_int2(src[i] << 5, __float_as_int(ea[i]));
    }
}

// ---------------------------------------------------------------------------
// Hop 1 (all nodes): Yh[n] = half( x[n] + sum_e half(x[src_e]) * w_e )
// fp32 residual + fp32 accumulate; fp16 gathers and fp16 output row.
// ---------------------------------------------------------------------------
__global__ void __launch_bounds__(256) hop1_kernel(
    const float4* __restrict__ x4)
{
    int n    = (blockIdx.x * blockDim.x + threadIdx.x) >> 5;
    int lane = threadIdx.x & 31;
    if (n >= N_NODES) return;

    float4 acc = __ldg(&x4[(size_t)n * D4 + lane]);
    int s0 = __ldg(&g_off[n])     + __ldg(&g_bsum[n >> 10]);
    int e0 = __ldg(&g_off[n + 1]) + __ldg(&g_bsum[(n + 1) >> 10]);

    const uint2* xh2 = reinterpret_cast<const uint2*>(g_xh);

    #pragma unroll 4
    for (int j = s0; j < e0; ++j) {
        int2 e = __ldg(&g_epack[j]);               // uniform broadcast, 1 wf
        float w = __int_as_float(e.y);
        uint2 h = __ldg(&xh2[(size_t)(unsigned)e.x + lane]);  // fp16 row, 2 wf
        __half2 h01 = *reinterpret_cast<__half2*>(&h.x);
        __half2 h23 = *reinterpret_cast<__half2*>(&h.y);
        float2 f01 = __half22float2(h01);
        float2 f23 = __half22float2(h23);
        acc.x += f01.x * w;
        acc.y += f01.y * w;
        acc.z += f23.x * w;
        acc.w += f23.y * w;
    }
    __half2 o01 = __floats2half2_rn(acc.x, acc.y);
    __half2 o23 = __floats2half2_rn(acc.z, acc.w);
    uint2 p;
    p.x = *reinterpret_cast<unsigned int*>(&o01);
    p.y = *reinterpret_cast<unsigned int*>(&o23);
    reinterpret_cast<uint2*>(g_Yh)[(size_t)n * D4 + lane] = p;
}

// ---------------------------------------------------------------------------
// Hop 2 fused with selection gather: one warp per OUTPUT row, fp16 gathers,
// fp32 accumulate, fp32 output.
//   out[i] = Yh[sel[i]] + sum_{e in CSR(sel[i])} Yh[src_e] * w_e
// ---------------------------------------------------------------------------
__global__ void __launch_bounds__(256) hop2_direct_kernel(
    const int* __restrict__ sel,
    float4* __restrict__ out4)
{
    int row  = (blockIdx.x * blockDim.x + threadIdx.x) >> 5;
    int lane = threadIdx.x & 31;
    if (row >= N_POOL) return;

    int n = __ldg(sel + row);
    const uint2* yh2 = reinterpret_cast<const uint2*>(g_Yh);

    // residual from fp16 Y row
    uint2 r = __ldg(&yh2[(size_t)n * D4 + lane]);
    __half2 r01 = *reinterpret_cast<__half2*>(&r.x);
    __half2 r23 = *reinterpret_cast<__half2*>(&r.y);
    float2 q01 = __half22float2(r01);
    float2 q23 = __half22float2(r23);
    float4 acc = make_float4(q01.x, q01.y, q23.x, q23.y);

    int s0 = __ldg(&g_off[n])     + __ldg(&g_bsum[n >> 10]);
    int e0 = __ldg(&g_off[n + 1]) + __ldg(&g_bsum[(n + 1) >> 10]);

    #pragma unroll 4
    for (int j = s0; j < e0; ++j) {
        int2 e = __ldg(&g_epack[j]);               // uniform broadcast
        float w = __int_as_float(e.y);
        uint2 h = __ldg(&yh2[(size_t)(unsigned)e.x + lane]);
        __half2 h01 = *reinterpret_cast<__half2*>(&h.x);
        __half2 h23 = *reinterpret_cast<__half2*>(&h.y);
        float2 f01 = __half22float2(h01);
        float2 f23 = __half22float2(h23);
        acc.x += f01.x * w;
        acc.y += f01.y * w;
        acc.z += f23.x * w;
        acc.w += f23.y * w;
    }
    out4[(size_t)row * D4 + lane] = acc;
}

// ---------------------------------------------------------------------------
extern "C" void kernel_launch(void* const* d_in, const int* in_sizes, int n_in,
                              void* d_out, int out_size)
{
    const float* x    = (const float*)d_in[0];   // [N, 128] f32
    const float* ea   = (const float*)d_in[1];   // [E] f32
    const int*   eidx = (const int*)d_in[2];     // [2, E] int32
    const int*   sel  = (const int*)d_in[3];     // [N_pool] int32
    float* out = (float*)d_out;

    const int* src = eidx;            // row 0 (x_j sources)
    const int* dst = eidx + N_EDGES;  // row 1 (aggregation targets)

    const float4* x4 = reinterpret_cast<const float4*>(x);
    const int TB = 256;

    // CSR build + fp16 convert: (hist|convert) -> fused scan -> reorder
    hist_convert_kernel<<<(N4 + TB - 1) / TB, TB>>>(
        reinterpret_cast<const int4*>(dst), x4);
    scan_fused_kernel<<<NBLK, SCAN_B>>>();
    reorder_kernel<<<(N_EDGES + TB - 1) / TB, TB>>>(src, dst, ea);

    // hop 1 (all nodes, fp16 gather, fp16 out):  Yh = half(x + A@x)
    hop1_kernel<<<(N_NODES * 32 + TB - 1) / TB, TB>>>(x4);

    // hop 2 fused with output gather: out[i] = (Yh + A@Yh)[sel[i]]
    hop2_direct_kernel<<<(N_POOL * 32 + TB - 1) / TB, TB>>>(
        sel, (float4*)out);
}